// round 7
// baseline (speedup 1.0000x reference)
#include <cuda_runtime.h>
#include <cuda_bf16.h>
#include <cstdint>

// ---------------------------------------------------------------------------
// GCN graph conv:
//   out_deg = clip(segsum(1, src), 1);  in_deg = clip(segsum(1, dst), 1)
//   h   = tanh( (feat * out_deg^-0.5) @ W )            [N, 128]
//   out = segsum( h[src] * ew , dst ) * in_deg^-0.5    [N, 128]
//
// src/dst are INT32 on device (jax x64 disabled) despite int64 annotation.
// ---------------------------------------------------------------------------

#define IN_FEATS  256
#define OUT_FEATS 128
#define MAX_N     100000

__device__ int   g_outdeg[MAX_N];
__device__ int   g_indeg [MAX_N];
__device__ __align__(16) float g_h[(size_t)MAX_N * OUT_FEATS];

// ---------------------------------------------------------------------------
// One kernel zeroes both degree arrays and the output (float4 stores).
__global__ void zero_all_kernel(float4* __restrict__ out4, int n4, int n_nodes) {
    int i = blockIdx.x * blockDim.x + threadIdx.x;
    if (i < n4) out4[i] = make_float4(0.f, 0.f, 0.f, 0.f);
    if (i < n_nodes) { g_outdeg[i] = 0; g_indeg[i] = 0; }
}

__global__ void degree_kernel(const int* __restrict__ src,
                              const int* __restrict__ dst, int E) {
    int e = blockIdx.x * blockDim.x + threadIdx.x;
    if (e < E) {
        atomicAdd(&g_outdeg[src[e]], 1);
        atomicAdd(&g_indeg [dst[e]], 1);
    }
}

// ---------------------------------------------------------------------------
// SGEMM, fused out-degree pre-scale on A, tanh epilogue.
// Tile: 128x128, BK=16, double-buffered smem, 256 threads, 8x8 per thread.
#define BM 128
#define BN 128
#define BK 16
#define TM 8
#define TN 8

__global__ __launch_bounds__(256)
void gemm_tanh_kernel(const float* __restrict__ feat,
                      const float* __restrict__ W, int M) {
    __shared__ __align__(16) float As[2][BK][BM];   // 16 KB
    __shared__ __align__(16) float Bs[2][BK][BN];   // 16 KB

    const int t    = threadIdx.x;
    const int row0 = blockIdx.x * BM;
    const int tx   = t & 15;
    const int ty   = t >> 4;

    // A loader: thread t covers feat[row0 + t/2][k0 + (t&1)*8 .. +7] (2 float4)
    const int arow = t >> 1;
    const int acol = (t & 1) * 8;
    float ascale = 0.0f;
    const bool arow_ok = (row0 + arow) < M;
    if (arow_ok) {
        int dg = g_outdeg[row0 + arow];
        ascale = rsqrtf((float)(dg > 0 ? dg : 1));
    }
    // B loader: thread t covers W[k0 + t/16][((2t)&31)*4 .. +7] (2 float4)
    const int brow = t >> 4;
    const int bcol = ((2 * t) & 31) * 4;

    float acc[TM][TN];
#pragma unroll
    for (int i = 0; i < TM; ++i)
#pragma unroll
        for (int j = 0; j < TN; ++j) acc[i][j] = 0.0f;

    float4 a0, a1, b0, b1;
    // -------- load tile 0 --------
    a0 = a1 = make_float4(0.f, 0.f, 0.f, 0.f);
    if (arow_ok) {
        const float* ap = feat + (size_t)(row0 + arow) * IN_FEATS + acol;
        a0 = *(const float4*)(ap);
        a1 = *(const float4*)(ap + 4);
    }
    {
        const float* bp = W + (size_t)brow * OUT_FEATS + bcol;
        b0 = *(const float4*)(bp);
        b1 = *(const float4*)(bp + 4);
    }
    {
        As[0][acol + 0][arow] = a0.x * ascale;
        As[0][acol + 1][arow] = a0.y * ascale;
        As[0][acol + 2][arow] = a0.z * ascale;
        As[0][acol + 3][arow] = a0.w * ascale;
        As[0][acol + 4][arow] = a1.x * ascale;
        As[0][acol + 5][arow] = a1.y * ascale;
        As[0][acol + 6][arow] = a1.z * ascale;
        As[0][acol + 7][arow] = a1.w * ascale;
        *(float4*)&Bs[0][brow][bcol]     = b0;
        *(float4*)&Bs[0][brow][bcol + 4] = b1;
    }
    __syncthreads();

    const int NSTEP = IN_FEATS / BK;   // 16
#pragma unroll 1
    for (int s = 0; s < NSTEP; ++s) {
        const int buf  = s & 1;
        const int nbuf = buf ^ 1;
        const bool has_next = (s + 1) < NSTEP;

        // prefetch next tile to registers
        if (has_next) {
            const int k0 = (s + 1) * BK;
            a0 = a1 = make_float4(0.f, 0.f, 0.f, 0.f);
            if (arow_ok) {
                const float* ap = feat + (size_t)(row0 + arow) * IN_FEATS + k0 + acol;
                a0 = *(const float4*)(ap);
                a1 = *(const float4*)(ap + 4);
            }
            const float* bp = W + (size_t)(k0 + brow) * OUT_FEATS + bcol;
            b0 = *(const float4*)(bp);
            b1 = *(const float4*)(bp + 4);
        }

        // compute on current buffer
#pragma unroll
        for (int k = 0; k < BK; ++k) {
            float ra[TM], rb[TN];
#pragma unroll
            for (int i = 0; i < TM; ++i) ra[i] = As[buf][k][ty * TM + i];
#pragma unroll
            for (int j = 0; j < TN; ++j) rb[j] = Bs[buf][k][tx * TN + j];
#pragma unroll
            for (int i = 0; i < TM; ++i)
#pragma unroll
                for (int j = 0; j < TN; ++j) acc[i][j] += ra[i] * rb[j];
        }

        // stage next tile into the other buffer
        if (has_next) {
            As[nbuf][acol + 0][arow] = a0.x * ascale;
            As[nbuf][acol + 1][arow] = a0.y * ascale;
            As[nbuf][acol + 2][arow] = a0.z * ascale;
            As[nbuf][acol + 3][arow] = a0.w * ascale;
            As[nbuf][acol + 4][arow] = a1.x * ascale;
            As[nbuf][acol + 5][arow] = a1.y * ascale;
            As[nbuf][acol + 6][arow] = a1.z * ascale;
            As[nbuf][acol + 7][arow] = a1.w * ascale;
            *(float4*)&Bs[nbuf][brow][bcol]     = b0;
            *(float4*)&Bs[nbuf][brow][bcol + 4] = b1;
        }
        __syncthreads();
    }

    // tanh epilogue + store to g_h
#pragma unroll
    for (int i = 0; i < TM; ++i) {
        int r = row0 + ty * TM + i;
        if (r < M) {
            float* dstp = g_h + (size_t)r * OUT_FEATS + tx * TN;
            float4 o0, o1;
            o0.x = tanhf(acc[i][0]); o0.y = tanhf(acc[i][1]);
            o0.z = tanhf(acc[i][2]); o0.w = tanhf(acc[i][3]);
            o1.x = tanhf(acc[i][4]); o1.y = tanhf(acc[i][5]);
            o1.z = tanhf(acc[i][6]); o1.w = tanhf(acc[i][7]);
            *(float4*)(dstp)     = o0;
            *(float4*)(dstp + 4) = o1;
        }
    }
}

// ---------------------------------------------------------------------------
// One warp per edge. lane -> one float4: vector gather, scale, vector
// 128-bit atomicAdd into out. Folds in_deg^-0.5 into the edge weight.
__global__ __launch_bounds__(256)
void scatter_kernel(const int* __restrict__ src,
                    const int* __restrict__ dst,
                    const float* __restrict__ ew,
                    float* __restrict__ out, int E) {
    const int lane = threadIdx.x & 31;
    const int e = blockIdx.x * (blockDim.x >> 5) + (threadIdx.x >> 5);
    if (e >= E) return;

    const int s = __ldg(src + e);
    const int d = __ldg(dst + e);
    const int dg = __ldg(&g_indeg[d]);
    const float w = __ldg(ew + e) * rsqrtf((float)(dg > 0 ? dg : 1));

    float4 v = __ldg((const float4*)g_h + (size_t)s * (OUT_FEATS / 4) + lane);
    v.x *= w; v.y *= w; v.z *= w; v.w *= w;

    float4* p = (float4*)(out + (size_t)d * OUT_FEATS) + lane;
    atomicAdd(p, v);
}

// ---------------------------------------------------------------------------
extern "C" void kernel_launch(void* const* d_in, const int* in_sizes, int n_in,
                              void* d_out, int out_size) {
    const float* feat = (const float*)d_in[0];
    const float* W    = (const float*)d_in[1];
    const float* ew   = (const float*)d_in[2];
    const int*   src  = (const int*)d_in[3];   // int32 on device
    const int*   dst  = (const int*)d_in[4];
    float*       out  = (float*)d_out;

    const int M = in_sizes[0] / IN_FEATS;   // 100000
    const int E = in_sizes[2];              // 1600000

    const int n4 = out_size / 4;            // 3.2M float4
    zero_all_kernel<<<(n4 + 255) / 256, 256>>>((float4*)out, n4, M);
    degree_kernel<<<(E + 255) / 256, 256>>>(src, dst, E);
    gemm_tanh_kernel<<<(M + BM - 1) / BM, 256>>>(feat, W, M);
    {
        const int warps_per_block = 256 / 32;
        const int blocks = (E + warps_per_block - 1) / warps_per_block;
        scatter_kernel<<<blocks, 256>>>(src, dst, ew, out, E);
    }
}

// round 8
// speedup vs baseline: 1.5600x; 1.5600x over previous
#include <cuda_runtime.h>
#include <cuda_bf16.h>
#include <cstdint>

// ---------------------------------------------------------------------------
// GCN graph conv, CSR two-phase aggregation (no float atomics):
//   out_deg/in_deg from edge list; h = tanh((feat*outdeg^-.5) @ W)
//   CSR by dst -> per-node gather of h[src]*ew, scaled by indeg^-.5.
// src/dst are INT32 on device (jax x64 disabled) despite int64 annotation.
// ---------------------------------------------------------------------------

#define IN_FEATS  256
#define OUT_FEATS 128
#define MAX_N     100000
#define MAX_E     1600000

__device__ int  g_outdeg[MAX_N];
__device__ int  g_indeg [MAX_N];
__device__ int  g_start [MAX_N];
__device__ int  g_cursor[MAX_N];
__device__ int  g_bsum  [128];
__device__ __align__(8)  int2  g_edge[MAX_E];              // {src, f32 ew bits}
__device__ __align__(16) float g_h[(size_t)MAX_N * OUT_FEATS];

// ---------------------------------------------------------------------------
__global__ void zero_deg_kernel(int n) {
    int i = blockIdx.x * blockDim.x + threadIdx.x;
    if (i < n) { g_outdeg[i] = 0; g_indeg[i] = 0; }
}

__global__ void degree_kernel(const int* __restrict__ src,
                              const int* __restrict__ dst, int E) {
    int e = blockIdx.x * blockDim.x + threadIdx.x;
    if (e < E) {
        atomicAdd(&g_outdeg[src[e]], 1);
        atomicAdd(&g_indeg [dst[e]], 1);
    }
}

// --------------------------- exclusive scan of g_indeg ---------------------
__global__ void scan_block_kernel(int n) {           // grid=ceil(n/1024), block=1024
    __shared__ int sh[1024];
    const int tid = threadIdx.x;
    const int i = blockIdx.x * 1024 + tid;
    int v = (i < n) ? g_indeg[i] : 0;
    sh[tid] = v;
    __syncthreads();
#pragma unroll
    for (int off = 1; off < 1024; off <<= 1) {
        int t = (tid >= off) ? sh[tid - off] : 0;
        __syncthreads();
        sh[tid] += t;
        __syncthreads();
    }
    if (i < n) g_start[i] = sh[tid] - v;             // exclusive within block
    if (tid == 1023) g_bsum[blockIdx.x] = sh[1023];  // block total
}

__global__ void scan_bsums_kernel(int nb) {          // 1 block, 128 threads
    __shared__ int sh[128];
    const int tid = threadIdx.x;
    int v = (tid < nb) ? g_bsum[tid] : 0;
    sh[tid] = v;
    __syncthreads();
#pragma unroll
    for (int off = 1; off < 128; off <<= 1) {
        int t = (tid >= off) ? sh[tid - off] : 0;
        __syncthreads();
        sh[tid] += t;
        __syncthreads();
    }
    if (tid < nb) g_bsum[tid] = sh[tid] - v;         // exclusive block offsets
}

__global__ void scan_add_kernel(int n) {             // block=1024 (i>>10 match)
    int i = blockIdx.x * 1024 + threadIdx.x;
    if (i < n) {
        int s = g_start[i] + g_bsum[i >> 10];
        g_start[i]  = s;
        g_cursor[i] = s;
    }
}

// --------------------------- CSR fill --------------------------------------
__global__ void fill_kernel(const int* __restrict__ src,
                            const int* __restrict__ dst,
                            const float* __restrict__ ew, int E) {
    int e = blockIdx.x * blockDim.x + threadIdx.x;
    if (e < E) {
        int d = dst[e];
        int slot = atomicAdd(&g_cursor[d], 1);
        g_edge[slot] = make_int2(src[e], __float_as_int(ew[e]));
    }
}

// ---------------------------------------------------------------------------
// SGEMM (R6 config: BK=8 single-buffer — measured faster than BK=16 DB),
// fused out-degree pre-scale on A, tanh epilogue.
#define BM 128
#define BN 128
#define BK 8
#define TM 8
#define TN 8

__global__ __launch_bounds__(256)
void gemm_tanh_kernel(const float* __restrict__ feat,
                      const float* __restrict__ W, int M) {
    __shared__ __align__(16) float As[BK][BM];
    __shared__ __align__(16) float Bs[BK][BN];

    const int t    = threadIdx.x;
    const int row0 = blockIdx.x * BM;
    const int tx   = t & 15;
    const int ty   = t >> 4;

    const int arow = t >> 1;
    const int acol = (t & 1) * 4;
    float ascale = 0.0f;
    const bool arow_ok = (row0 + arow) < M;
    if (arow_ok) {
        int dg = g_outdeg[row0 + arow];
        ascale = rsqrtf((float)(dg > 0 ? dg : 1));
    }
    const int bk = t >> 5;
    const int bn = (t & 31) * 4;

    float acc[TM][TN];
#pragma unroll
    for (int i = 0; i < TM; ++i)
#pragma unroll
        for (int j = 0; j < TN; ++j) acc[i][j] = 0.0f;

    for (int k0 = 0; k0 < IN_FEATS; k0 += BK) {
        float4 av = make_float4(0.f, 0.f, 0.f, 0.f);
        if (arow_ok)
            av = *(const float4*)(feat + (size_t)(row0 + arow) * IN_FEATS + k0 + acol);
        As[acol + 0][arow] = av.x * ascale;
        As[acol + 1][arow] = av.y * ascale;
        As[acol + 2][arow] = av.z * ascale;
        As[acol + 3][arow] = av.w * ascale;

        float4 bv = *(const float4*)(W + (size_t)(k0 + bk) * OUT_FEATS + bn);
        *(float4*)&Bs[bk][bn] = bv;

        __syncthreads();

#pragma unroll
        for (int k = 0; k < BK; ++k) {
            float ra[TM], rb[TN];
#pragma unroll
            for (int i = 0; i < TM; ++i) ra[i] = As[k][ty * TM + i];
#pragma unroll
            for (int j = 0; j < TN; ++j) rb[j] = Bs[k][tx * TN + j];
#pragma unroll
            for (int i = 0; i < TM; ++i)
#pragma unroll
                for (int j = 0; j < TN; ++j) acc[i][j] += ra[i] * rb[j];
        }
        __syncthreads();
    }

#pragma unroll
    for (int i = 0; i < TM; ++i) {
        int r = row0 + ty * TM + i;
        if (r < M) {
            float* dstp = g_h + (size_t)r * OUT_FEATS + tx * TN;
            float4 o0, o1;
            o0.x = tanhf(acc[i][0]); o0.y = tanhf(acc[i][1]);
            o0.z = tanhf(acc[i][2]); o0.w = tanhf(acc[i][3]);
            o1.x = tanhf(acc[i][4]); o1.y = tanhf(acc[i][5]);
            o1.z = tanhf(acc[i][6]); o1.w = tanhf(acc[i][7]);
            *(float4*)(dstp)     = o0;
            *(float4*)(dstp + 4) = o1;
        }
    }
}

// ---------------------------------------------------------------------------
// Aggregate: one warp per dst node. Lane owns one float4 (4 of 128 feats).
// Registers accumulate; output written exactly once (no zero-pass needed).
__global__ __launch_bounds__(256)
void aggregate_kernel(float* __restrict__ out, int N) {
    const int lane = threadIdx.x & 31;
    const int n = blockIdx.x * (blockDim.x >> 5) + (threadIdx.x >> 5);
    if (n >= N) return;

    const int begin = g_start[n];
    const int cnt   = g_indeg[n];

    float4 acc = make_float4(0.f, 0.f, 0.f, 0.f);
    const float4* h4 = (const float4*)g_h;

    int j = 0;
    for (; j + 2 <= cnt; j += 2) {
        int2 e0 = g_edge[begin + j];
        int2 e1 = g_edge[begin + j + 1];
        float4 v0 = __ldg(h4 + (size_t)e0.x * (OUT_FEATS / 4) + lane);
        float4 v1 = __ldg(h4 + (size_t)e1.x * (OUT_FEATS / 4) + lane);
        float w0 = __int_as_float(e0.y);
        float w1 = __int_as_float(e1.y);
        acc.x = fmaf(v0.x, w0, acc.x); acc.y = fmaf(v0.y, w0, acc.y);
        acc.z = fmaf(v0.z, w0, acc.z); acc.w = fmaf(v0.w, w0, acc.w);
        acc.x = fmaf(v1.x, w1, acc.x); acc.y = fmaf(v1.y, w1, acc.y);
        acc.z = fmaf(v1.z, w1, acc.z); acc.w = fmaf(v1.w, w1, acc.w);
    }
    if (j < cnt) {
        int2 e0 = g_edge[begin + j];
        float4 v0 = __ldg(h4 + (size_t)e0.x * (OUT_FEATS / 4) + lane);
        float w0 = __int_as_float(e0.y);
        acc.x = fmaf(v0.x, w0, acc.x); acc.y = fmaf(v0.y, w0, acc.y);
        acc.z = fmaf(v0.z, w0, acc.z); acc.w = fmaf(v0.w, w0, acc.w);
    }

    const float sc = rsqrtf((float)(cnt > 0 ? cnt : 1));
    acc.x *= sc; acc.y *= sc; acc.z *= sc; acc.w *= sc;
    ((float4*)(out + (size_t)n * OUT_FEATS))[lane] = acc;
}

// ---------------------------------------------------------------------------
extern "C" void kernel_launch(void* const* d_in, const int* in_sizes, int n_in,
                              void* d_out, int out_size) {
    const float* feat = (const float*)d_in[0];
    const float* W    = (const float*)d_in[1];
    const float* ew   = (const float*)d_in[2];
    const int*   src  = (const int*)d_in[3];   // int32 on device
    const int*   dst  = (const int*)d_in[4];
    float*       out  = (float*)d_out;

    const int M = in_sizes[0] / IN_FEATS;   // 100000
    const int E = in_sizes[2];              // 1600000
    const int nb = (M + 1023) / 1024;       // 98 scan blocks

    zero_deg_kernel<<<(M + 255) / 256, 256>>>(M);
    degree_kernel<<<(E + 255) / 256, 256>>>(src, dst, E);
    scan_block_kernel<<<nb, 1024>>>(M);
    scan_bsums_kernel<<<1, 128>>>(nb);
    scan_add_kernel<<<nb, 1024>>>(M);
    fill_kernel<<<(E + 255) / 256, 256>>>(src, dst, ew, E);
    gemm_tanh_kernel<<<(M + BM - 1) / BM, 256>>>(feat, W, M);
    {
        const int warps_per_block = 256 / 32;
        const int blocks = (M + warps_per_block - 1) / warps_per_block;
        aggregate_kernel<<<blocks, 256>>>(out, M);
    }
}

// round 10
// speedup vs baseline: 2.0712x; 1.3277x over previous
#include <cuda_runtime.h>
#include <cuda_bf16.h>
#include <cstdint>

// ---------------------------------------------------------------------------
// GCN graph conv, CSR two-phase aggregation + split-bf16 mma.sync GEMM.
//   h = tanh((feat*outdeg^-.5) @ W)  via 3-term bf16 split (HMMA, f32 acc)
//   out[n] = (sum_{e: dst=n} h[src_e]*ew_e) * indeg^-.5   (CSR gather)
// src/dst are INT32 on device (jax x64 disabled) despite int64 annotation.
// NOTE: harness compiles PTX at .target sm_103 (no 'a') -> tcgen05 is
// unavailable; mma.sync (baseline PTX) is the tensor path that works.
// ---------------------------------------------------------------------------

#define IN_FEATS  256
#define OUT_FEATS 128
#define MAX_N     100000
#define MAX_E     1600000

__device__ int  g_outdeg[MAX_N];
__device__ int  g_indeg [MAX_N];
__device__ int  g_start [MAX_N];
__device__ int  g_cursor[MAX_N];
__device__ int  g_bsum  [128];
__device__ __align__(8)  int2  g_edge[MAX_E];              // {src, f32 ew bits}
__device__ __align__(16) float g_h[(size_t)MAX_N * OUT_FEATS];
// W transposed + bf16-split: Wt[n][k] = W[k][n]
__device__ __align__(16) __nv_bfloat16 g_Wt_hi[OUT_FEATS * IN_FEATS];
__device__ __align__(16) __nv_bfloat16 g_Wt_lo[OUT_FEATS * IN_FEATS];

// ======================= graph-prep kernels =================================
__global__ void zero_deg_kernel(int n) {
    int i = blockIdx.x * blockDim.x + threadIdx.x;
    if (i < n) { g_outdeg[i] = 0; g_indeg[i] = 0; }
}

__global__ void degree_kernel(const int* __restrict__ src,
                              const int* __restrict__ dst, int E) {
    int e = blockIdx.x * blockDim.x + threadIdx.x;
    if (e < E) {
        atomicAdd(&g_outdeg[src[e]], 1);
        atomicAdd(&g_indeg [dst[e]], 1);
    }
}

__global__ void scan_block_kernel(int n) {           // grid=ceil(n/1024), block=1024
    __shared__ int sh[1024];
    const int tid = threadIdx.x;
    const int i = blockIdx.x * 1024 + tid;
    int v = (i < n) ? g_indeg[i] : 0;
    sh[tid] = v;
    __syncthreads();
#pragma unroll
    for (int off = 1; off < 1024; off <<= 1) {
        int t = (tid >= off) ? sh[tid - off] : 0;
        __syncthreads();
        sh[tid] += t;
        __syncthreads();
    }
    if (i < n) g_start[i] = sh[tid] - v;
    if (tid == 1023) g_bsum[blockIdx.x] = sh[1023];
}

__global__ void scan_bsums_kernel(int nb) {          // 1 block, 128 threads
    __shared__ int sh[128];
    const int tid = threadIdx.x;
    int v = (tid < nb) ? g_bsum[tid] : 0;
    sh[tid] = v;
    __syncthreads();
#pragma unroll
    for (int off = 1; off < 128; off <<= 1) {
        int t = (tid >= off) ? sh[tid - off] : 0;
        __syncthreads();
        sh[tid] += t;
        __syncthreads();
    }
    if (tid < nb) g_bsum[tid] = sh[tid] - v;
}

__global__ void scan_add_kernel(int n) {             // block=1024
    int i = blockIdx.x * 1024 + threadIdx.x;
    if (i < n) {
        int s = g_start[i] + g_bsum[i >> 10];
        g_start[i]  = s;
        g_cursor[i] = s;
    }
}

__global__ void fill_kernel(const int* __restrict__ src,
                            const int* __restrict__ dst,
                            const float* __restrict__ ew, int E) {
    int e = blockIdx.x * blockDim.x + threadIdx.x;
    if (e < E) {
        int d = dst[e];
        int slot = atomicAdd(&g_cursor[d], 1);
        g_edge[slot] = make_int2(src[e], __float_as_int(ew[e]));
    }
}

// W[256][128] f32 -> transposed split bf16 Wt[n][k]
__global__ void wsplit_kernel(const float* __restrict__ W) {
    int idx = blockIdx.x * blockDim.x + threadIdx.x;
    if (idx < IN_FEATS * OUT_FEATS) {
        int k = idx >> 7;            // 0..255
        int n = idx & 127;           // 0..127
        float x = W[idx];
        __nv_bfloat16 hi = __float2bfloat16(x);
        float lo = x - __bfloat162float(hi);
        g_Wt_hi[n * IN_FEATS + k] = hi;
        g_Wt_lo[n * IN_FEATS + k] = __float2bfloat16(lo);
    }
}

// ======================= split-bf16 mma.sync GEMM ===========================
// CTA: 128x128 tile, 8 warps (2m x 4n), warp tile 64x32, K chunks of 64.
// Smem tiles padded to 72 elems/row -> conflict-free 32-bit fragment LDS.
#define KC       64
#define NCHUNK   (IN_FEATS / KC)     // 4
#define TSTRIDE  72                  // elements per smem row (pad 64+8)
#define TROWB    (TSTRIDE * 2)       // 144 bytes
#define TILE_B   (128 * TROWB)       // 18432 bytes per tile
#define SM_AHI   0
#define SM_ALO   (SM_AHI + TILE_B)
#define SM_BHI   (SM_ALO + TILE_B)
#define SM_BLO   (SM_BHI + TILE_B)
#define SM_TOT   (SM_BLO + TILE_B)   // 73728 bytes

__device__ __forceinline__ uint32_t pack2bf(float a, float b) {
    __nv_bfloat162 t = __floats2bfloat162_rn(a, b);
    return *reinterpret_cast<uint32_t*>(&t);
}

#define MMA_BF16(c, a, b)                                                     \
    asm volatile(                                                             \
        "mma.sync.aligned.m16n8k16.row.col.f32.bf16.bf16.f32 "                \
        "{%0,%1,%2,%3}, {%4,%5,%6,%7}, {%8,%9}, {%0,%1,%2,%3};"               \
        : "+f"((c)[0]), "+f"((c)[1]), "+f"((c)[2]), "+f"((c)[3])              \
        : "r"((a)[0]), "r"((a)[1]), "r"((a)[2]), "r"((a)[3]),                 \
          "r"((b)[0]), "r"((b)[1]))

__global__ __launch_bounds__(256)
void gemm_mma_kernel(const float* __restrict__ feat, int M) {
    extern __shared__ __align__(16) char dsm[];
    const int tid  = threadIdx.x;
    const int lane = tid & 31;
    const int w    = tid >> 5;
    const int g    = lane >> 2;       // 0..7
    const int t    = lane & 3;        // 0..3
    const int m0   = (w >> 2) * 64;   // warp m-offset in tile
    const int n0   = (w & 3) * 32;    // warp n-offset in tile
    const int row0 = blockIdx.x * 128;

    // staging assignment: thread covers (row = tid/2, khalf = (tid&1)*32)
    const int srow = tid >> 1;
    const int skh  = (tid & 1) * 32;
    const bool rok = (row0 + srow) < M;
    float ascale = 0.0f;
    if (rok) {
        int dg = g_outdeg[row0 + srow];
        ascale = rsqrtf((float)(dg > 0 ? dg : 1));
    }

    float acc[4][4][4];
#pragma unroll
    for (int i = 0; i < 4; ++i)
#pragma unroll
        for (int j = 0; j < 4; ++j)
#pragma unroll
            for (int q = 0; q < 4; ++q) acc[i][j][q] = 0.0f;

#pragma unroll 1
    for (int c = 0; c < NCHUNK; ++c) {
        // ---- stage A (f32 -> bf16 hi/lo with ascale) ----
        {
            const float* ap = feat + (size_t)(row0 + srow) * IN_FEATS + c * KC + skh;
            char* dsthi = dsm + SM_AHI + srow * TROWB + skh * 2;
            char* dstlo = dsm + SM_ALO + srow * TROWB + skh * 2;
#pragma unroll
            for (int i = 0; i < 4; ++i) {            // 4 x 8 elems
                float4 f0 = make_float4(0.f, 0.f, 0.f, 0.f);
                float4 f1 = make_float4(0.f, 0.f, 0.f, 0.f);
                if (rok) {
                    f0 = __ldg((const float4*)(ap + i * 8));
                    f1 = __ldg((const float4*)(ap + i * 8 + 4));
                }
                f0.x *= ascale; f0.y *= ascale; f0.z *= ascale; f0.w *= ascale;
                f1.x *= ascale; f1.y *= ascale; f1.z *= ascale; f1.w *= ascale;
                float h[8] = {f0.x, f0.y, f0.z, f0.w, f1.x, f1.y, f1.z, f1.w};
                uint4 hv, lv;
                float hi0, hi1;
                hi0 = __bfloat162float(__float2bfloat16(h[0]));
                hi1 = __bfloat162float(__float2bfloat16(h[1]));
                hv.x = pack2bf(h[0], h[1]); lv.x = pack2bf(h[0]-hi0, h[1]-hi1);
                hi0 = __bfloat162float(__float2bfloat16(h[2]));
                hi1 = __bfloat162float(__float2bfloat16(h[3]));
                hv.y = pack2bf(h[2], h[3]); lv.y = pack2bf(h[2]-hi0, h[3]-hi1);
                hi0 = __bfloat162float(__float2bfloat16(h[4]));
                hi1 = __bfloat162float(__float2bfloat16(h[5]));
                hv.z = pack2bf(h[4], h[5]); lv.z = pack2bf(h[4]-hi0, h[5]-hi1);
                hi0 = __bfloat162float(__float2bfloat16(h[6]));
                hi1 = __bfloat162float(__float2bfloat16(h[7]));
                hv.w = pack2bf(h[6], h[7]); lv.w = pack2bf(h[6]-hi0, h[7]-hi1);
                *(uint4*)(dsthi + i * 16) = hv;
                *(uint4*)(dstlo + i * 16) = lv;
            }
        }
        // ---- stage B (preconverted bf16; Wt row n = srow) ----
        {
            const __nv_bfloat16* bh = g_Wt_hi + srow * IN_FEATS + c * KC + skh;
            const __nv_bfloat16* bl = g_Wt_lo + srow * IN_FEATS + c * KC + skh;
            char* dsthi = dsm + SM_BHI + srow * TROWB + skh * 2;
            char* dstlo = dsm + SM_BLO + srow * TROWB + skh * 2;
#pragma unroll
            for (int i = 0; i < 4; ++i) {            // 4 x uint4 = 32 bf16
                *(uint4*)(dsthi + i * 16) = __ldg((const uint4*)(bh + i * 8));
                *(uint4*)(dstlo + i * 16) = __ldg((const uint4*)(bl + i * 8));
            }
        }
        __syncthreads();

        // ---- compute: 4 k16 steps ----
#pragma unroll
        for (int ks = 0; ks < 4; ++ks) {
            uint32_t ah[4][4], al[4][4];
#pragma unroll
            for (int mf = 0; mf < 4; ++mf) {
                int ro = (m0 + mf * 16 + g) * TROWB + ks * 32 + t * 4;
                ah[mf][0] = *(const uint32_t*)(dsm + SM_AHI + ro);
                ah[mf][1] = *(const uint32_t*)(dsm + SM_AHI + ro + 8 * TROWB);
                ah[mf][2] = *(const uint32_t*)(dsm + SM_AHI + ro + 16);
                ah[mf][3] = *(const uint32_t*)(dsm + SM_AHI + ro + 8 * TROWB + 16);
                al[mf][0] = *(const uint32_t*)(dsm + SM_ALO + ro);
                al[mf][1] = *(const uint32_t*)(dsm + SM_ALO + ro + 8 * TROWB);
                al[mf][2] = *(const uint32_t*)(dsm + SM_ALO + ro + 16);
                al[mf][3] = *(const uint32_t*)(dsm + SM_ALO + ro + 8 * TROWB + 16);
            }
            uint32_t bh[4][2], bl[4][2];
#pragma unroll
            for (int nf = 0; nf < 4; ++nf) {
                int no = (n0 + nf * 8 + g) * TROWB + ks * 32 + t * 4;
                bh[nf][0] = *(const uint32_t*)(dsm + SM_BHI + no);
                bh[nf][1] = *(const uint32_t*)(dsm + SM_BHI + no + 16);
                bl[nf][0] = *(const uint32_t*)(dsm + SM_BLO + no);
                bl[nf][1] = *(const uint32_t*)(dsm + SM_BLO + no + 16);
            }
#pragma unroll
            for (int mf = 0; mf < 4; ++mf)
#pragma unroll
                for (int nf = 0; nf < 4; ++nf) {
                    MMA_BF16(acc[mf][nf], ah[mf], bh[nf]);
                    MMA_BF16(acc[mf][nf], ah[mf], bl[nf]);
                    MMA_BF16(acc[mf][nf], al[mf], bh[nf]);
                }
        }
        __syncthreads();
    }

    // ---- epilogue: tanh -> g_h ----
#pragma unroll
    for (int mf = 0; mf < 4; ++mf) {
        int r0g = row0 + m0 + mf * 16 + g;
        int r1g = r0g + 8;
#pragma unroll
        for (int nf = 0; nf < 4; ++nf) {
            int col = n0 + nf * 8 + t * 2;
            if (r0g < M) {
                float2 o;
                o.x = tanhf(acc[mf][nf][0]);
                o.y = tanhf(acc[mf][nf][1]);
                *(float2*)(g_h + (size_t)r0g * OUT_FEATS + col) = o;
            }
            if (r1g < M) {
                float2 o;
                o.x = tanhf(acc[mf][nf][2]);
                o.y = tanhf(acc[mf][nf][3]);
                *(float2*)(g_h + (size_t)r1g * OUT_FEATS + col) = o;
            }
        }
    }
}

// ======================= aggregate ==========================================
__global__ __launch_bounds__(256)
void aggregate_kernel(float* __restrict__ out, int N) {
    const int lane = threadIdx.x & 31;
    const int n = blockIdx.x * (blockDim.x >> 5) + (threadIdx.x >> 5);
    if (n >= N) return;

    const int begin = g_start[n];
    const int cnt   = g_indeg[n];

    float4 acc = make_float4(0.f, 0.f, 0.f, 0.f);
    const float4* h4 = (const float4*)g_h;

    int j = 0;
    for (; j + 2 <= cnt; j += 2) {
        int2 e0 = g_edge[begin + j];
        int2 e1 = g_edge[begin + j + 1];
        float4 v0 = __ldg(h4 + (size_t)e0.x * (OUT_FEATS / 4) + lane);
        float4 v1 = __ldg(h4 + (size_t)e1.x * (OUT_FEATS / 4) + lane);
        float w0 = __int_as_float(e0.y);
        float w1 = __int_as_float(e1.y);
        acc.x = fmaf(v0.x, w0, acc.x); acc.y = fmaf(v0.y, w0, acc.y);
        acc.z = fmaf(v0.z, w0, acc.z); acc.w = fmaf(v0.w, w0, acc.w);
        acc.x = fmaf(v1.x, w1, acc.x); acc.y = fmaf(v1.y, w1, acc.y);
        acc.z = fmaf(v1.z, w1, acc.z); acc.w = fmaf(v1.w, w1, acc.w);
    }
    if (j < cnt) {
        int2 e0 = g_edge[begin + j];
        float4 v0 = __ldg(h4 + (size_t)e0.x * (OUT_FEATS / 4) + lane);
        float w0 = __int_as_float(e0.y);
        acc.x = fmaf(v0.x, w0, acc.x); acc.y = fmaf(v0.y, w0, acc.y);
        acc.z = fmaf(v0.z, w0, acc.z); acc.w = fmaf(v0.w, w0, acc.w);
    }

    const float sc = rsqrtf((float)(cnt > 0 ? cnt : 1));
    acc.x *= sc; acc.y *= sc; acc.z *= sc; acc.w *= sc;
    ((float4*)(out + (size_t)n * OUT_FEATS))[lane] = acc;
}

// ---------------------------------------------------------------------------
extern "C" void kernel_launch(void* const* d_in, const int* in_sizes, int n_in,
                              void* d_out, int out_size) {
    const float* feat = (const float*)d_in[0];
    const float* W    = (const float*)d_in[1];
    const float* ew   = (const float*)d_in[2];
    const int*   src  = (const int*)d_in[3];   // int32 on device
    const int*   dst  = (const int*)d_in[4];
    float*       out  = (float*)d_out;

    const int M = in_sizes[0] / IN_FEATS;   // 100000
    const int E = in_sizes[2];              // 1600000
    const int nb = (M + 1023) / 1024;       // 98 scan blocks

    cudaFuncSetAttribute(gemm_mma_kernel,
                         cudaFuncAttributeMaxDynamicSharedMemorySize, SM_TOT);

    zero_deg_kernel<<<(M + 255) / 256, 256>>>(M);
    degree_kernel<<<(E + 255) / 256, 256>>>(src, dst, E);
    scan_block_kernel<<<nb, 1024>>>(M);
    scan_bsums_kernel<<<1, 128>>>(nb);
    scan_add_kernel<<<nb, 1024>>>(M);
    fill_kernel<<<(E + 255) / 256, 256>>>(src, dst, ew, E);
    wsplit_kernel<<<(IN_FEATS * OUT_FEATS + 255) / 256, 256>>>(W);
    gemm_mma_kernel<<<(M + 127) / 128, 256, SM_TOT>>>(feat, M);
    {
        const int warps_per_block = 256 / 32;
        const int blocks = (M + warps_per_block - 1) / warps_per_block;
        aggregate_kernel<<<blocks, 256>>>(out, M);
    }
}